// round 16
// baseline (speedup 1.0000x reference)
#include <cuda_runtime.h>
#include <cuda_fp16.h>
#include <cstdint>

// ============================================================================
// relu(x @ W^T + b): M=131072, N=256, K=256, fp32.  Base sm_103 target.
// R13: CTA 128x128, 4 warps, warp tile 64x64 (R11 macro shape), fp16 m16n8k16.
// NEW: the CTA's whole A tile (128x256) is converted fp32->fp16 into smem ONCE
// in the prologue (LDG.128 -> cvt.rn.f16x2 -> swizzled STS.64). Mainloop A is
// pure ldmatrix (zero LDS.64, zero cvt). B: W pre-converted fp16 -> cp.async
// 3-stage -> ldmatrix (zero cvt). grid(2,1024) for L2 x reuse.
// smem: 64KB A (resident, 512B swizzled rows) + 3 x 16KB B stages = 112KB.
// ============================================================================

static constexpr int DK = 256;
static constexpr int DN = 256;
static constexpr int BM = 128;
static constexpr int BN = 128;
static constexpr int KC = 32;                  // B chunk: 32 k
static constexpr int THREADS = 128;
static constexpr int NSTAGE = 3;

static constexpr int A_REGION = BM * DK * 2;   // 65536: fp16 A, 512B rows
static constexpr int B_BYTES  = BN * 128;      // 16384: fp16 B, 128B padded rows
static constexpr int SMEM_DYN = A_REGION + NSTAGE * B_BYTES;   // 114688

__device__ __half W_h[DN * DK];                // 128KB fp16 weight scratch

// ---------------------------------------------------------------------------
__device__ __forceinline__ uint32_t smem_u32(const void* p) {
    uint32_t a;
    asm("{ .reg .u64 t; cvta.to.shared.u64 t, %1; cvt.u32.u64 %0, t; }" : "=r"(a) : "l"(p));
    return a;
}
__device__ __forceinline__ void cp_async16(uint32_t dst, const void* src) {
    asm volatile("cp.async.cg.shared.global [%0], [%1], 16;" :: "r"(dst), "l"(src));
}
__device__ __forceinline__ void ldsm_x4(uint32_t* d, uint32_t addr) {
    asm volatile("ldmatrix.sync.aligned.m8n8.x4.shared.b16 {%0,%1,%2,%3}, [%4];"
                 : "=r"(d[0]), "=r"(d[1]), "=r"(d[2]), "=r"(d[3]) : "r"(addr));
}
__device__ __forceinline__ uint32_t pack_f16(float hi, float lo) {
    uint32_t d;
    asm("cvt.rn.f16x2.f32 %0, %1, %2;" : "=r"(d) : "f"(hi), "f"(lo));
    return d;
}
__device__ __forceinline__ void sts64(uint32_t addr, uint32_t v0, uint32_t v1) {
    asm volatile("st.shared.v2.b32 [%0], {%1, %2};" :: "r"(addr), "r"(v0), "r"(v1) : "memory");
}
__device__ __forceinline__ void mma_f16(float* d, const uint32_t* a,
                                        uint32_t b0, uint32_t b1) {
    asm volatile(
        "mma.sync.aligned.m16n8k16.row.col.f32.f16.f16.f32 "
        "{%0,%1,%2,%3}, {%4,%5,%6,%7}, {%8,%9}, {%0,%1,%2,%3};"
        : "+f"(d[0]), "+f"(d[1]), "+f"(d[2]), "+f"(d[3])
        : "r"(a[0]), "r"(a[1]), "r"(a[2]), "r"(a[3]), "r"(b0), "r"(b1));
}
// B tile swizzle (128B rows)
__device__ __forceinline__ uint32_t swzB(int row, int seg16) {
    return (uint32_t)row * 128u + (uint32_t)((seg16 * 16) ^ ((row & 7) * 16));
}

// ---------------------------------------------------------------------------
// pre-pass: W (fp32) -> fp16
__global__ void convert_W_kernel(const float* __restrict__ W) {
    int i = blockIdx.x * 256 + threadIdx.x;     // 16384 float4
    float4 v = reinterpret_cast<const float4*>(W)[i];
    uint2 o;
    o.x = pack_f16(v.y, v.x);
    o.y = pack_f16(v.w, v.z);
    reinterpret_cast<uint2*>(W_h)[i] = o;
}

// ---------------------------------------------------------------------------
__global__ __launch_bounds__(THREADS, 2)
void gemm_relu_f16_kernel(const float* __restrict__ x,
                          const float* __restrict__ bias, float* __restrict__ out) {
    extern __shared__ __align__(1024) char smem_raw[];
    const uint32_t base = smem_u32(smem_raw);       // A region (64KB)
    const uint32_t Bbase = base + A_REGION;         // B stages

    const int tid = threadIdx.x;
    const int wid = tid >> 5;      // 0..3
    const int lid = tid & 31;
    const int g   = lid >> 2;      // 0..7
    const int t   = lid & 3;       // 0..3
    const int wm  = wid & 1;       // 2 x 64-row m-tiles
    const int wn  = wid >> 1;      // 2 x 64-col n-tiles
    const int n0  = blockIdx.x * BN;      // N fastest-varying -> L2 x reuse
    const int m0  = blockIdx.y * BM;
    const __half* Wp = W_h + (size_t)n0 * DK;

    // ldmatrix lane role
    const int mx = lid >> 3;       // 0..3
    const int r  = lid & 7;
    const uint32_t xr = (uint32_t)(r * 16);

    // B fragment rows (128B rows)
    uint32_t b_row[4];
    #pragma unroll
    for (int ntp = 0; ntp < 4; ntp++)
        b_row[ntp] = (uint32_t)(wn * 64 + ntp * 16 + (mx & 1) * 8 + r) * 128u;
    const uint32_t b_sel = (uint32_t)((mx >> 1) * 16);

    // A fragment rows (512B rows in the resident fp16 A region)
    uint32_t a_rowoff[4];
    uint32_t a_rowxor[4];
    #pragma unroll
    for (int mt = 0; mt < 4; mt++) {
        int row = wm * 64 + mt * 16 + (mx & 1) * 8 + r;
        a_rowoff[mt] = (uint32_t)row * 512u;
        a_rowxor[mt] = (uint32_t)((row & 7) * 16);
    }
    const uint32_t a_sel = (uint32_t)((mx >> 1) * 16);

    // B load roles
    const int lrowB = tid >> 2;      // 0..31
    const int lsegB = tid & 3;       // 0..3

    // ---- prologue part 1: B chunks 0,1 via cp.async (land while A converts)
    #pragma unroll
    for (int pc = 0; pc < 2; pc++) {
        const uint32_t S = Bbase + (uint32_t)pc * B_BYTES;
        const int k0 = pc * KC;
        #pragma unroll
        for (int i = 0; i < 4; i++) {
            int row = i * 32 + lrowB;
            cp_async16(S + swzB(row, lsegB), Wp + (size_t)row * DK + k0 + lsegB * 8);
        }
        asm volatile("cp.async.commit_group;" ::: "memory");
    }

    // ---- prologue part 2: convert whole A tile (128x256 fp32 -> fp16, once)
    // 8192 float4 / 128 threads = 64 per thread; row = idx/64, seg = idx%64.
    {
        const float4* xs = reinterpret_cast<const float4*>(x + (size_t)m0 * DK);
        #pragma unroll 8
        for (int i = 0; i < 64; i++) {
            int idx = i * 128 + tid;
            int row = idx >> 6;
            int seg = idx & 63;
            float4 v = xs[(size_t)row * 64 + seg];
            uint32_t lo = pack_f16(v.y, v.x);
            uint32_t hi = pack_f16(v.w, v.z);
            uint32_t addr = base + (uint32_t)row * 512u
                          + (uint32_t)((seg * 8) ^ ((row & 7) * 16));
            sts64(addr, lo, hi);
        }
    }

    float acc[4][8][4];              // warp tile 64x64
    #pragma unroll
    for (int mt = 0; mt < 4; mt++)
        #pragma unroll
        for (int nt = 0; nt < 8; nt++)
            #pragma unroll
            for (int j = 0; j < 4; j++) acc[mt][nt][j] = 0.0f;

    int stage = 0, dst = 2;
    #pragma unroll 1
    for (int kc = 0; kc < 8; kc++) {
        if (kc < 7)
            asm volatile("cp.async.wait_group 1;" ::: "memory");
        else
            asm volatile("cp.async.wait_group 0;" ::: "memory");  // drain last chunk
        __syncthreads();   // also covers the one-time A STS at kc=0

        const uint32_t Bs = Bbase + (uint32_t)stage * B_BYTES;

        if (kc < 6) {
            const uint32_t Bd = Bbase + (uint32_t)dst * B_BYTES;
            const int k2 = (kc + 2) * KC;
            #pragma unroll
            for (int i = 0; i < 4; i++) {
                int row = i * 32 + lrowB;
                cp_async16(Bd + swzB(row, lsegB),
                           Wp + (size_t)row * DK + k2 + lsegB * 8);
            }
            asm volatile("cp.async.commit_group;" ::: "memory");
        }

        #pragma unroll
        for (int kk = 0; kk < 2; kk++) {      // 2 x k16 per chunk
            const uint32_t kb = (uint32_t)(kc * 2 + kk);   // k16 block index

            // ---- B fragments: 4 n16 tiles, fp16 ldmatrix
            uint32_t bb[4][4];
            const uint32_t bcol = ((uint32_t)(kk * 32) + b_sel) ^ xr;
            #pragma unroll
            for (int ntp = 0; ntp < 4; ntp++)
                ldsm_x4(bb[ntp], Bs + b_row[ntp] + bcol);

            // ---- A fragments: 4 m16 tiles, fp16 ldmatrix from resident region
            uint32_t a[4][4];
            #pragma unroll
            for (int mt = 0; mt < 4; mt++) {
                uint32_t acol = (kb * 32 + a_sel) ^ a_rowxor[mt];
                ldsm_x4(a[mt], base + a_rowoff[mt] + acol);
            }

            // ---- 32 MMAs (m16n8k16)
            #pragma unroll
            for (int mt = 0; mt < 4; mt++) {
                #pragma unroll
                for (int ntp = 0; ntp < 4; ntp++) {
                    mma_f16(acc[mt][2 * ntp],     a[mt], bb[ntp][0], bb[ntp][2]);
                    mma_f16(acc[mt][2 * ntp + 1], a[mt], bb[ntp][1], bb[ntp][3]);
                }
            }
        }

        stage = (stage == NSTAGE - 1) ? 0 : stage + 1;
        dst   = (dst == NSTAGE - 1) ? 0 : dst + 1;
    }

    // ---- epilogue: bias + relu, float2 stores
    const int m_base = m0 + wm * 64;
    const int n_base = n0 + wn * 64;
    #pragma unroll
    for (int nt = 0; nt < 8; nt++) {
        const int col = n_base + nt * 8 + 2 * t;
        const float2 bv = *reinterpret_cast<const float2*>(bias + col);
        #pragma unroll
        for (int mt = 0; mt < 4; mt++) {
            const int row0 = m_base + mt * 16 + g;
            float2 v0;
            v0.x = fmaxf(acc[mt][nt][0] + bv.x, 0.0f);
            v0.y = fmaxf(acc[mt][nt][1] + bv.y, 0.0f);
            *reinterpret_cast<float2*>(out + (size_t)row0 * DN + col) = v0;
            float2 v1;
            v1.x = fmaxf(acc[mt][nt][2] + bv.x, 0.0f);
            v1.y = fmaxf(acc[mt][nt][3] + bv.y, 0.0f);
            *reinterpret_cast<float2*>(out + (size_t)(row0 + 8) * DN + col) = v1;
        }
    }
}

// ---------------------------------------------------------------------------
extern "C" void kernel_launch(void* const* d_in, const int* in_sizes, int n_in,
                              void* d_out, int out_size) {
    const float* x = (const float*)d_in[0];
    const float* W = (const float*)d_in[1];
    const float* b = (const float*)d_in[2];
    float* out = (float*)d_out;

    int Brows = in_sizes[0] / DK;     // 131072
    dim3 grid(DN / BN, Brows / BM);   // (2, 1024)

    convert_W_kernel<<<DN * DK / 4 / 256, 256>>>(W);   // 64 blocks

    cudaFuncSetAttribute(gemm_relu_f16_kernel,
                         cudaFuncAttributeMaxDynamicSharedMemorySize, SMEM_DYN);
    gemm_relu_f16_kernel<<<grid, THREADS, SMEM_DYN>>>(x, b, out);
}